// round 9
// baseline (speedup 1.0000x reference)
#include <cuda_runtime.h>
#include <math.h>

// Problem constants
#define BT   1024   // BS*T
#define NEN  64     // entities
#define ED   128    // entity dim
#define HYPD 256    // hypernet hidden
#define NA   16     // agents
#define NHD  4      // heads
#define HD   64     // head dim
#define EMB  32
#define NTHR 512

typedef unsigned long long u64;

// ---- packed fp32x2 helpers (Blackwell FFMA2; bitwise == 2x scalar fp32) ----
__device__ __forceinline__ void ffma2(u64 &d, u64 a, u64 b) {
    asm("fma.rn.f32x2 %0, %1, %2, %0;" : "+l"(d) : "l"(a), "l"(b));
}
__device__ __forceinline__ u64 splat2(float x) {
    u64 r; asm("mov.b64 %0, {%1, %1};" : "=l"(r) : "f"(x)); return r;
}
__device__ __forceinline__ float2 unpack2(u64 v) {
    float lo, hi; asm("mov.b64 {%0, %1}, %2;" : "=f"(lo), "=f"(hi) : "l"(v));
    return make_float2(lo, hi);
}

// -------- global scratch (static device arrays; no allocation) --------
__device__ float g_w1[BT * NA * EMB];
__device__ float g_b1[BT * EMB];
__device__ float g_wf[BT * EMB];
__device__ float g_vv[BT];

struct Ptrs { const float* p[31]; };

#define SMEM_FLOATS 57568

// ---------------------------------------------------------------------
// Tiled GEMM, K-paired f32x2 (zero packing MOVs in the hot loop).
// sOut[R][C] = epi( sA[R][K] @ gW[C][K]^T + bias ).  512 threads.
// wt: K-major tile wt[c][16] with per-c k-rotation swizzle.
// Thread -> cg = tid % NCG (NCG = C/4), rg = tid / NCG.
// Columns per thread: c = cg + j*NCG, j = 0..3 (strided).
// ---------------------------------------------------------------------
template<int R, int C, int K, bool BIAS, bool RELU, bool AMASK>
__device__ __forceinline__ void gemm(const float* __restrict__ sA,
                                     const float* __restrict__ gW,
                                     const float* __restrict__ gB,
                                     float* __restrict__ sOut,
                                     float* __restrict__ wt,
                                     const float* __restrict__ sAm,
                                     int tid)
{
    constexpr int KT  = 16;
    constexpr int TC  = 4;
    constexpr int NCG = C / TC;
    constexpr int NRG = NTHR / NCG;
    constexpr int RPG = (R + NRG - 1) / NRG;
    constexpr int NT  = K / KT;
    constexpr int K4  = KT / 4;                      // 4
    constexpr int TOT = C * K4;
    constexpr int LPT = (TOT + NTHR - 1) / NTHR;

    const int cg = tid % NCG;
    const int rg = tid / NCG;
    const int r0 = rg * RPG;
    const bool active = (r0 < R);
    const int swo = 4 * ((cg >> 1) & 3);             // k-rotation (same for all j)

    // staging coords
    int sc[LPT], sk4[LPT];
    bool sp[LPT];
#pragma unroll
    for (int l = 0; l < LPT; l++) {
        int idx = tid + l * NTHR;
        sp[l]  = (idx < TOT);
        sc[l]  = (idx < TOT) ? (idx / K4) : 0;
        sk4[l] = (idx < TOT) ? (idx % K4) : 0;
    }

    u64 acc[RPG][TC];
#pragma unroll
    for (int r = 0; r < RPG; r++)
#pragma unroll
        for (int j = 0; j < TC; j++) acc[r][j] = 0ULL;

    // prologue: fetch tile 0
    float4 st[LPT];
#pragma unroll
    for (int l = 0; l < LPT; l++)
        if (sp[l]) st[l] = *(const float4*)(gW + sc[l] * K + 4 * sk4[l]);

    for (int t = 0; t < NT; t++) {
        const int k0 = t * KT;
        __syncthreads();   // wt free
#pragma unroll
        for (int l = 0; l < LPT; l++) {
            if (sp[l]) {
                int c   = sc[l];
                int off = (4 * sk4[l] + 4 * ((c >> 1) & 3)) & 15;
                *(float4*)(wt + c * KT + off) = st[l];
            }
        }
        __syncthreads();   // wt visible
        if (t + 1 < NT) {
#pragma unroll
            for (int l = 0; l < LPT; l++)
                if (sp[l]) st[l] = *(const float4*)(gW + sc[l] * K + (k0 + KT) + 4 * sk4[l]);
        }
        if (active) {
#pragma unroll
            for (int kk = 0; kk < KT; kk += 4) {
                const int koff = (kk + swo) & 15;
                ulonglong2 w[TC];
#pragma unroll
                for (int j = 0; j < TC; j++)
                    w[j] = *(const ulonglong2*)(wt + (cg + j * NCG) * KT + koff);
#pragma unroll
                for (int r = 0; r < RPG; r++) {
                    ulonglong2 av = *(const ulonglong2*)(sA + (r0 + r) * K + k0 + kk);
#pragma unroll
                    for (int j = 0; j < TC; j++) {
                        ffma2(acc[r][j], av.x, w[j].x);
                        ffma2(acc[r][j], av.y, w[j].y);
                    }
                }
            }
        }
    }

    if (active) {
#pragma unroll
        for (int r = 0; r < RPG; r++) {
            int rr = r0 + r;
            float m = 1.f;
            if (AMASK) m = (sAm[rr] != 0.f) ? 0.f : 1.f;
#pragma unroll
            for (int j = 0; j < TC; j++) {
                int c = cg + j * NCG;
                float2 f = unpack2(acc[r][j]);
                float v = f.x + f.y;
                if (BIAS) v += gB[c];
                if (RELU) v = fmaxf(v, 0.f);
                sOut[rr * C + c] = v * m;
            }
        }
    }
}

// ---------------------------------------------------------------------
extern __shared__ float smem[];

__global__ void __launch_bounds__(NTHR)
hyper_kernel(Ptrs P)
{
    const int b   = blockIdx.x;
    const int h   = blockIdx.y;
    const int tid = threadIdx.x;

    const float* entities = P.p[1];
    const int*   emask    = (const int*)P.p[2];
    const int    base     = 3 + h * 7;
    const float* fc1_w = P.p[base + 0];
    const float* fc1_b = P.p[base + 1];
    const float* qkv_w = P.p[base + 2];
    const float* out_w = P.p[base + 3];
    const float* out_b = P.p[base + 4];
    const float* fc2_w = P.p[base + 5];
    const float* fc2_b = P.p[base + 6];

    float* sX1    = smem;             // 16384
    float* sK     = smem + 16384;     // 16384
    float* sV     = smem + 32768;     // 16384
    float* sQ     = smem + 49152;     // 4096 (E 8192 during fc1)
    float* sE     = smem + 49152;
    float* sAttn  = smem + 53248;     // 4096 (wtile V/Q here: 4096)
    float* sL     = sX1;              // 64x65 logits (X1 dead)
    float* sX3    = sX1 + 8192;       // 16x32
    float* sAttn2 = sK;               // 16x256 (K dead)
    float* sEm    = smem + 57408;     // 64
    float* sAm    = smem + 57472;     // 16
    float* sInv   = smem + 57488;     // 64

    __shared__ int sAnyZero;
    if (tid == 0) sAnyZero = 0;
    __syncthreads();

    if (tid < NEN) {
        int m = emask[b * NEN + tid];
        sEm[tid] = (float)m;
        if (tid < NA) sAm[tid] = (float)m;
        if (m == 0) atomicOr(&sAnyZero, 1);
    }
    {
        const float4* src = (const float4*)(entities + (size_t)b * NEN * ED);
        float4* dst = (float4*)sE;
        for (int i = tid; i < NEN * ED / 4; i += NTHR) dst[i] = src[i];
    }
    __syncthreads();

    // fc1: x1 = relu(E @ fc1_w^T + b)   A@sE, wtile@sK, out@sX1
    gemm<64, 256, 128, true, true, false>(sE, fc1_w, fc1_b, sX1, sK, nullptr, tid);
    __syncthreads();

    // K gemm: A@sX1, wtile@sV, out@sK
    gemm<64, 256, 256, false, false, false>(sX1, qkv_w + 256 * 256, nullptr, sK, sV, nullptr, tid);
    __syncthreads();
    // V gemm: A@sX1, wtile@sAttn, out@sV
    gemm<64, 256, 256, false, false, false>(sX1, qkv_w + 512 * 256, nullptr, sV, sAttn, nullptr, tid);
    __syncthreads();
    // Q gemm (16 rows): A@sX1, wtile@sAttn, out@sQ
    gemm<16, 256, 256, false, false, false>(sX1, qkv_w, nullptr, sQ, sAttn, nullptr, tid);
    __syncthreads();

    const int anyZero = sAnyZero;

    // ---------- attention ----------
    // Phase 1: logits. t -> (jg = t>>6, hq = t&63); each thread: 8 j's.
    {
        const int jg = tid >> 6;
        const int hq = tid & 63;
        const int hh = hq >> 4;
        const int i  = hq & 15;
        const float am_i = sAm[i];
        const float scale = 0.125f;  // 1/sqrt(64)

        u64 qp[32];
        const ulonglong2* qrow = (const ulonglong2*)(sQ + i * HYPD + hh * HD);
#pragma unroll
        for (int d4 = 0; d4 < 16; d4++) {
            ulonglong2 q = qrow[d4];
            qp[2 * d4 + 0] = q.x;
            qp[2 * d4 + 1] = q.y;
        }

#pragma unroll
        for (int jj = 0; jj < 8; jj++) {
            int j = jg * 8 + jj;
            const ulonglong2* krow = (const ulonglong2*)(sK + j * HYPD + hh * HD);
            u64 a0 = 0ULL, a1 = 0ULL;
#pragma unroll
            for (int d4 = 0; d4 < 16; d4++) {
                ulonglong2 kv = krow[d4];
                ffma2(a0, qp[2 * d4 + 0], kv.x);
                ffma2(a1, qp[2 * d4 + 1], kv.y);
            }
            float2 f0 = unpack2(a0);
            float2 f1 = unpack2(a1);
            float s = (f0.x + f0.y) + (f1.x + f1.y);
            const bool keep = (am_i == 0.f) && (sEm[j] == 0.f);
            sL[hq * 65 + j] = keep ? (s * scale) : -1e30f;
        }
    }
    __syncthreads();

    // Phase 2: softmax per row (64 threads)
    if (tid < 64) {
        const int hq = tid;
        const int i  = hq & 15;
        const float am_i = sAm[i];
        const bool allm = (am_i != 0.f) || (anyZero == 0);
        float* lrow = sL + hq * 65;
        float mx = -1e30f;
        for (int j = 0; j < NEN; j++) mx = fmaxf(mx, lrow[j]);
        float sum = 0.f;
        for (int j = 0; j < NEN; j++) {
            float e = expf(lrow[j] - mx);
            sum += e;
            lrow[j] = e;
        }
        sInv[hq] = allm ? 0.f : (1.f / sum);
    }
    __syncthreads();

    // Phase 3: AV. t -> (dg = t>>6, hq = t&63); each thread: 8 d's.
    {
        const int dg = tid >> 6;
        const int hq = tid & 63;
        const int hh = hq >> 4;
        const int i  = hq & 15;
        const int d0 = dg * 8;
        const float* lrow = sL + hq * 65;
        u64 acc[4] = {0ULL, 0ULL, 0ULL, 0ULL};
        for (int j = 0; j < NEN; j++) {
            u64 ps = splat2(lrow[j]);
            const ulonglong2* vrow = (const ulonglong2*)(sV + j * HYPD + hh * HD + d0);
            ulonglong2 va = vrow[0];
            ulonglong2 vb = vrow[1];
            ffma2(acc[0], ps, va.x);
            ffma2(acc[1], ps, va.y);
            ffma2(acc[2], ps, vb.x);
            ffma2(acc[3], ps, vb.y);
        }
        const float inv = sInv[hq];
        float* arow = sAttn + i * HYPD + hh * HD + d0;
#pragma unroll
        for (int q = 0; q < 4; q++) {
            float2 f = unpack2(acc[q]);
            arow[2 * q + 0] = f.x * inv;
            arow[2 * q + 1] = f.y * inv;
        }
    }
    __syncthreads();

    // out projection: A@sAttn, wtile@sX1 (logits dead), out@sAttn2(=sK)
    gemm<16, 256, 256, true, false, true>(sAttn, out_w, out_b, sAttn2, sX1, sAm, tid);
    __syncthreads();

    // fc2: A@sAttn2, wtile@sX1, out@sX3 (sX1+8192)
    gemm<16, 32, 256, true, false, true>(sAttn2, fc2_w, fc2_b, sX3, sX1, sAm, tid);
    __syncthreads();

    // mode-specific reductions -> global scratch
    if (h == 0) {
        for (int idx = tid; idx < NA * EMB; idx += NTHR)
            g_w1[(size_t)b * NA * EMB + idx] = fabsf(sX3[idx]);
    } else if (h == 1) {
        if (tid < EMB) {
            float s = 0.f;
            for (int i = 0; i < NA; i++) s += sX3[i * EMB + tid];
            g_b1[b * EMB + tid] = s * (1.f / 16.f);
        }
    } else if (h == 2) {
        if (tid < EMB) {
            float s = 0.f;
            for (int i = 0; i < NA; i++) s += sX3[i * EMB + tid];
            g_wf[b * EMB + tid] = fabsf(s * (1.f / 16.f));
        }
    } else {
        if (tid < EMB) {
            float s = 0.f;
            for (int i = 0; i < NA; i++) s += sX3[i * EMB + tid];
            sInv[tid] = s;
        }
        __syncthreads();
        if (tid == 0) {
            float t = 0.f;
            for (int e = 0; e < EMB; e++) t += sInv[e];
            g_vv[b] = t * (1.f / 512.f);
        }
    }
}

// ---------------------------------------------------------------------
__global__ void __launch_bounds__(256)
mix_kernel(const float* __restrict__ qs, float* __restrict__ out)
{
    const int warp = threadIdx.x >> 5;
    const int lane = threadIdx.x & 31;
    const int b = blockIdx.x * 8 + warp;
    const int e = lane;

    float s = g_b1[b * EMB + e];
#pragma unroll
    for (int a = 0; a < NA; a++)
        s += qs[b * NA + a] * g_w1[(b * NA + a) * EMB + e];
    float hdn = (s > 0.f) ? s : expm1f(s);
    float t = hdn * g_wf[b * EMB + e];
#pragma unroll
    for (int off = 16; off > 0; off >>= 1)
        t += __shfl_xor_sync(0xFFFFFFFF, t, off);
    if (lane == 0) out[b] = t + g_vv[b];
}

// ---------------------------------------------------------------------
extern "C" void kernel_launch(void* const* d_in, const int* in_sizes, int n_in,
                              void* d_out, int out_size)
{
    Ptrs P;
    for (int i = 0; i < 31; i++) P.p[i] = (const float*)d_in[i];

    const size_t smem_bytes = (size_t)SMEM_FLOATS * sizeof(float);
    cudaFuncSetAttribute(hyper_kernel,
                         cudaFuncAttributeMaxDynamicSharedMemorySize,
                         (int)smem_bytes);

    hyper_kernel<<<dim3(BT, 4), NTHR, smem_bytes>>>(P);
    mix_kernel<<<BT / 8, 256>>>((const float*)d_in[0], (float*)d_out);
}

// round 10
// speedup vs baseline: 1.1501x; 1.1501x over previous
#include <cuda_runtime.h>
#include <math.h>

// Problem constants
#define BT   1024
#define NEN  64
#define ED   128
#define HYPD 256
#define NA   16
#define NHD  4
#define HD   64
#define EMB  32
#define NTHR 512

typedef unsigned long long u64;

__device__ __forceinline__ void ffma2(u64 &d, u64 a, u64 b) {
    asm("fma.rn.f32x2 %0, %1, %2, %0;" : "+l"(d) : "l"(a), "l"(b));
}
__device__ __forceinline__ u64 splat2(float x) {
    u64 r; asm("mov.b64 %0, {%1, %1};" : "=l"(r) : "f"(x)); return r;
}
__device__ __forceinline__ float2 unpack2(u64 v) {
    float lo, hi; asm("mov.b64 {%0, %1}, %2;" : "=f"(lo), "=f"(hi) : "l"(v));
    return make_float2(lo, hi);
}

// -------- global scratch --------
__device__ float g_w1[BT * NA * EMB];
__device__ float g_b1[BT * EMB];
__device__ float g_wf[BT * EMB];
__device__ float g_vv[BT];

struct Ptrs { const float* p[31]; };

// smem map (floats):
//  0     : x1T [256][66] = 16896   (later: sL 64x65=4160 @0; attn2T [256][18]=4608 @0; sX3 @8192)
//  16896 : sK 64x256 = 16384       (fc1: sET [128][66]=8448; after logits: attnT [256][18]=4608)
//  33280 : sV 64x256 = 16384
//  49664 : sQ 16x256 = 4096
//  53760 : wt staging 16*(256+4) = 4160 (shared by all gemms)
//  57920 : sEm 64 | 57984 : sAm 16 | 58000 : sInv 64  -> end 58064
#define SMEM_FLOATS 58064

#define X1T_OFF  0
#define X1T_ST   66
#define L_OFF    0
#define A2T_OFF  0
#define X3_OFF   8192
#define K_OFF    16896
#define ET_OFF   16896
#define ET_ST    66
#define ATT_OFF  16896
#define ATT_ST   18
#define V_OFF    33280
#define Q_OFF    49664
#define WT_OFF   53760
#define EM_OFF   57920
#define AM_OFF   57984
#define INV_OFF  58000

// ---------------------------------------------------------------------
// Row-paired f32x2 GEMM.  sOut = epi( A[R][K] @ gW[C][K]^T + bias )
// A given TRANSPOSED: sAT[k*AST + r].  Output row-major (OST==0) or
// transposed with stride OST.  512 threads.
// wt layout: [k][C+4] (k-row-major), KT=16.
// ---------------------------------------------------------------------
template<int R, int C, int K, int AST, int OST, bool BIAS, bool RELU, bool AMASK>
__device__ __forceinline__ void gemmT(const float* __restrict__ sAT,
                                      const float* __restrict__ gW,
                                      const float* __restrict__ gB,
                                      float* __restrict__ sOut,
                                      float* __restrict__ wt,
                                      const float* __restrict__ sAm,
                                      int tid)
{
    constexpr int KT  = 16;
    constexpr int CP  = C + 4;
    constexpr int NCG = C / 4;
    constexpr int NRG = NTHR / NCG;
    constexpr int RPG = (R + NRG - 1) / NRG;
    constexpr int RP  = RPG / 2;          // row pairs (0 when RPG==1)
    constexpr int NT  = K / KT;
    constexpr int K4  = KT / 4;
    constexpr int TOT = C * K4;
    constexpr int LPT = (TOT + NTHR - 1) / NTHR;

    const int cg = tid % NCG;
    const int rg = tid / NCG;
    const int r0 = rg * RPG;
    const int c0 = cg * 4;
    const bool active = (r0 < R);

    // staging coords
    int sc[LPT], sk4[LPT];
    bool sp[LPT];
#pragma unroll
    for (int l = 0; l < LPT; l++) {
        int idx = tid + l * NTHR;
        sp[l]  = (idx < TOT);
        sc[l]  = (idx < TOT) ? (idx / K4) : 0;
        sk4[l] = (idx < TOT) ? (idx % K4) : 0;
    }

    u64   accp[RP > 0 ? RP : 1][4];
    float accs[4];
    if (RP > 0) {
#pragma unroll
        for (int p = 0; p < RP; p++)
#pragma unroll
            for (int j = 0; j < 4; j++) accp[p][j] = 0ULL;
    } else {
#pragma unroll
        for (int j = 0; j < 4; j++) accs[j] = 0.f;
    }

    float4 st[LPT];
#pragma unroll
    for (int l = 0; l < LPT; l++)
        if (sp[l]) st[l] = *(const float4*)(gW + sc[l] * K + 4 * sk4[l]);

    for (int t = 0; t < NT; t++) {
        const int k0 = t * KT;
        __syncthreads();
#pragma unroll
        for (int l = 0; l < LPT; l++) {
            if (sp[l]) {
                int c  = sc[l];
                int kb = 4 * sk4[l];
                wt[(kb + 0) * CP + c] = st[l].x;
                wt[(kb + 1) * CP + c] = st[l].y;
                wt[(kb + 2) * CP + c] = st[l].z;
                wt[(kb + 3) * CP + c] = st[l].w;
            }
        }
        __syncthreads();
        if (t + 1 < NT) {
#pragma unroll
            for (int l = 0; l < LPT; l++)
                if (sp[l]) st[l] = *(const float4*)(gW + sc[l] * K + (k0 + KT) + 4 * sk4[l]);
        }
        if (active) {
#pragma unroll
            for (int k = 0; k < KT; k++) {
                const float4 w4 = *(const float4*)(wt + k * CP + c0);
                const float* arow = sAT + (k0 + k) * AST + r0;
                if (RP > 0) {
                    u64 ws0 = splat2(w4.x), ws1 = splat2(w4.y);
                    u64 ws2 = splat2(w4.z), ws3 = splat2(w4.w);
#pragma unroll
                    for (int p = 0; p < RP; p++) {
                        u64 ap = *(const u64*)(arow + 2 * p);
                        ffma2(accp[p][0], ap, ws0);
                        ffma2(accp[p][1], ap, ws1);
                        ffma2(accp[p][2], ap, ws2);
                        ffma2(accp[p][3], ap, ws3);
                    }
                } else {
                    float a = arow[0];
                    accs[0] += a * w4.x;
                    accs[1] += a * w4.y;
                    accs[2] += a * w4.z;
                    accs[3] += a * w4.w;
                }
            }
        }
    }

    if (active) {
        float4 bias = make_float4(0.f, 0.f, 0.f, 0.f);
        if (BIAS) {
            bias.x = gB[c0 + 0]; bias.y = gB[c0 + 1];
            bias.z = gB[c0 + 2]; bias.w = gB[c0 + 3];
        }
        if (RP > 0) {
#pragma unroll
            for (int p = 0; p < RP; p++) {
                int ra = r0 + 2 * p, rb = ra + 1;
                float ma = 1.f, mb = 1.f;
                if (AMASK) {
                    ma = (sAm[ra] != 0.f) ? 0.f : 1.f;
                    mb = (sAm[rb] != 0.f) ? 0.f : 1.f;
                }
#pragma unroll
                for (int j = 0; j < 4; j++) {
                    int c = c0 + j;
                    float bj = (j == 0) ? bias.x : (j == 1) ? bias.y : (j == 2) ? bias.z : bias.w;
                    float2 f = unpack2(accp[p][j]);
                    float va = f.x + bj, vb = f.y + bj;
                    if (RELU) { va = fmaxf(va, 0.f); vb = fmaxf(vb, 0.f); }
                    va *= ma; vb *= mb;
                    if (OST > 0) {
                        sOut[c * OST + ra] = va;
                        sOut[c * OST + rb] = vb;
                    } else {
                        sOut[ra * C + c] = va;
                        sOut[rb * C + c] = vb;
                    }
                }
            }
        } else {
            float m = 1.f;
            if (AMASK) m = (sAm[r0] != 0.f) ? 0.f : 1.f;
#pragma unroll
            for (int j = 0; j < 4; j++) {
                int c = c0 + j;
                float bj = (j == 0) ? bias.x : (j == 1) ? bias.y : (j == 2) ? bias.z : bias.w;
                float v = accs[j] + bj;
                if (RELU) v = fmaxf(v, 0.f);
                v *= m;
                if (OST > 0) sOut[c * OST + r0] = v;
                else         sOut[r0 * C + c] = v;
            }
        }
    }
}

// ---------------------------------------------------------------------
extern __shared__ float smem[];

__global__ void __launch_bounds__(NTHR)
hyper_kernel(Ptrs P)
{
    const int b   = blockIdx.x;
    const int h   = blockIdx.y;
    const int tid = threadIdx.x;

    const float* entities = P.p[1];
    const int*   emask    = (const int*)P.p[2];
    const int    base     = 3 + h * 7;
    const float* fc1_w = P.p[base + 0];
    const float* fc1_b = P.p[base + 1];
    const float* qkv_w = P.p[base + 2];
    const float* out_w = P.p[base + 3];
    const float* out_b = P.p[base + 4];
    const float* fc2_w = P.p[base + 5];
    const float* fc2_b = P.p[base + 6];

    float* sX1T   = smem + X1T_OFF;
    float* sK     = smem + K_OFF;
    float* sV     = smem + V_OFF;
    float* sQ     = smem + Q_OFF;
    float* sET    = smem + ET_OFF;
    float* sAttnT = smem + ATT_OFF;
    float* sL     = smem + L_OFF;
    float* sA2T   = smem + A2T_OFF;
    float* sX3    = smem + X3_OFF;
    float* sWT    = smem + WT_OFF;
    float* sEm    = smem + EM_OFF;
    float* sAm    = smem + AM_OFF;
    float* sInv   = smem + INV_OFF;

    __shared__ int sAnyZero;
    if (tid == 0) sAnyZero = 0;
    __syncthreads();

    if (tid < NEN) {
        int m = emask[b * NEN + tid];
        sEm[tid] = (float)m;
        if (tid < NA) sAm[tid] = (float)m;
        if (m == 0) atomicOr(&sAnyZero, 1);
    }
    // load entities transposed: sET[d][r], stride 66
    {
        const float4* src = (const float4*)(entities + (size_t)b * NEN * ED);
        for (int i = tid; i < NEN * ED / 4; i += NTHR) {
            float4 v = src[i];
            int r  = i / (ED / 4);
            int d0 = (i % (ED / 4)) * 4;
            sET[(d0 + 0) * ET_ST + r] = v.x;
            sET[(d0 + 1) * ET_ST + r] = v.y;
            sET[(d0 + 2) * ET_ST + r] = v.z;
            sET[(d0 + 3) * ET_ST + r] = v.w;
        }
    }
    __syncthreads();

    // fc1: x1T = relu(E @ fc1_w^T + b)^T     (A = ET, out transposed)
    gemmT<64, 256, 128, ET_ST, X1T_ST, true, true, false>(sET, fc1_w, fc1_b, sX1T, sWT, nullptr, tid);
    __syncthreads();

    // K gemm: out row-major sK
    gemmT<64, 256, 256, X1T_ST, 0, false, false, false>(sX1T, qkv_w + 256 * 256, nullptr, sK, sWT, nullptr, tid);
    __syncthreads();
    // V gemm
    gemmT<64, 256, 256, X1T_ST, 0, false, false, false>(sX1T, qkv_w + 512 * 256, nullptr, sV, sWT, nullptr, tid);
    __syncthreads();
    // Q gemm (16 rows)
    gemmT<16, 256, 256, X1T_ST, 0, false, false, false>(sX1T, qkv_w, nullptr, sQ, sWT, nullptr, tid);
    __syncthreads();

    const int anyZero = sAnyZero;

    // ---------- attention ----------
    // Phase 1: logits (x1T dead -> sL @0)
    {
        const int jg = tid >> 6;
        const int hq = tid & 63;
        const int hh = hq >> 4;
        const int i  = hq & 15;
        const float am_i = sAm[i];
        const float scale = 0.125f;

        u64 qp[32];
        const ulonglong2* qrow = (const ulonglong2*)(sQ + i * HYPD + hh * HD);
#pragma unroll
        for (int d4 = 0; d4 < 16; d4++) {
            ulonglong2 q = qrow[d4];
            qp[2 * d4 + 0] = q.x;
            qp[2 * d4 + 1] = q.y;
        }
#pragma unroll
        for (int jj = 0; jj < 8; jj++) {
            int j = jg * 8 + jj;
            const ulonglong2* krow = (const ulonglong2*)(sK + j * HYPD + hh * HD);
            u64 a0 = 0ULL, a1 = 0ULL;
#pragma unroll
            for (int d4 = 0; d4 < 16; d4++) {
                ulonglong2 kv = krow[d4];
                ffma2(a0, qp[2 * d4 + 0], kv.x);
                ffma2(a1, qp[2 * d4 + 1], kv.y);
            }
            float2 f0 = unpack2(a0);
            float2 f1 = unpack2(a1);
            float s = (f0.x + f0.y) + (f1.x + f1.y);
            const bool keep = (am_i == 0.f) && (sEm[j] == 0.f);
            sL[hq * 65 + j] = keep ? (s * scale) : -1e30f;
        }
    }
    __syncthreads();

    // Phase 2: softmax per row
    if (tid < 64) {
        const int hq = tid;
        const int i  = hq & 15;
        const float am_i = sAm[i];
        const bool allm = (am_i != 0.f) || (anyZero == 0);
        float* lrow = sL + hq * 65;
        float mx = -1e30f;
        for (int j = 0; j < NEN; j++) mx = fmaxf(mx, lrow[j]);
        float sum = 0.f;
        for (int j = 0; j < NEN; j++) {
            float e = expf(lrow[j] - mx);
            sum += e;
            lrow[j] = e;
        }
        sInv[hq] = allm ? 0.f : (1.f / sum);
    }
    __syncthreads();

    // Phase 3: AV -> attnT (K region dead)
    {
        const int dg = tid >> 6;
        const int hq = tid & 63;
        const int hh = hq >> 4;
        const int i  = hq & 15;
        const int d0 = dg * 8;
        const float* lrow = sL + hq * 65;
        u64 acc[4] = {0ULL, 0ULL, 0ULL, 0ULL};
        for (int j = 0; j < NEN; j++) {
            u64 ps = splat2(lrow[j]);
            const ulonglong2* vrow = (const ulonglong2*)(sV + j * HYPD + hh * HD + d0);
            ulonglong2 va = vrow[0];
            ulonglong2 vb = vrow[1];
            ffma2(acc[0], ps, va.x);
            ffma2(acc[1], ps, va.y);
            ffma2(acc[2], ps, vb.x);
            ffma2(acc[3], ps, vb.y);
        }
        const float inv = sInv[hq];
#pragma unroll
        for (int q = 0; q < 4; q++) {
            float2 f = unpack2(acc[q]);
            int c = hh * HD + d0 + 2 * q;
            sAttnT[(c + 0) * ATT_ST + i] = f.x * inv;
            sAttnT[(c + 1) * ATT_ST + i] = f.y * inv;
        }
    }
    __syncthreads();

    // out projection: A = attnT, out = attn2T @0 (sL dead), masked
    gemmT<16, 256, 256, ATT_ST, ATT_ST, true, false, true>(sAttnT, out_w, out_b, sA2T, sWT, sAm, tid);
    __syncthreads();

    // fc2: A = attn2T, out = sX3 row-major, masked
    gemmT<16, 32, 256, ATT_ST, 0, true, false, true>(sA2T, fc2_w, fc2_b, sX3, sWT, sAm, tid);
    __syncthreads();

    // reductions
    if (h == 0) {
        for (int idx = tid; idx < NA * EMB; idx += NTHR)
            g_w1[(size_t)b * NA * EMB + idx] = fabsf(sX3[idx]);
    } else if (h == 1) {
        if (tid < EMB) {
            float s = 0.f;
            for (int i = 0; i < NA; i++) s += sX3[i * EMB + tid];
            g_b1[b * EMB + tid] = s * (1.f / 16.f);
        }
    } else if (h == 2) {
        if (tid < EMB) {
            float s = 0.f;
            for (int i = 0; i < NA; i++) s += sX3[i * EMB + tid];
            g_wf[b * EMB + tid] = fabsf(s * (1.f / 16.f));
        }
    } else {
        if (tid < EMB) {
            float s = 0.f;
            for (int i = 0; i < NA; i++) s += sX3[i * EMB + tid];
            sInv[tid] = s;
        }
        __syncthreads();
        if (tid == 0) {
            float t = 0.f;
            for (int e = 0; e < EMB; e++) t += sInv[e];
            g_vv[b] = t * (1.f / 512.f);
        }
    }
}

// ---------------------------------------------------------------------
__global__ void __launch_bounds__(256)
mix_kernel(const float* __restrict__ qs, float* __restrict__ out)
{
    const int warp = threadIdx.x >> 5;
    const int lane = threadIdx.x & 31;
    const int b = blockIdx.x * 8 + warp;
    const int e = lane;

    float s = g_b1[b * EMB + e];
#pragma unroll
    for (int a = 0; a < NA; a++)
        s += qs[b * NA + a] * g_w1[(b * NA + a) * EMB + e];
    float hdn = (s > 0.f) ? s : expm1f(s);
    float t = hdn * g_wf[b * EMB + e];
#pragma unroll
    for (int off = 16; off > 0; off >>= 1)
        t += __shfl_xor_sync(0xFFFFFFFF, t, off);
    if (lane == 0) out[b] = t + g_vv[b];
}

// ---------------------------------------------------------------------
extern "C" void kernel_launch(void* const* d_in, const int* in_sizes, int n_in,
                              void* d_out, int out_size)
{
    Ptrs P;
    for (int i = 0; i < 31; i++) P.p[i] = (const float*)d_in[i];

    const size_t smem_bytes = (size_t)SMEM_FLOATS * sizeof(float); // 232,256 B
    cudaFuncSetAttribute(hyper_kernel,
                         cudaFuncAttributeMaxDynamicSharedMemorySize,
                         (int)smem_bytes);

    hyper_kernel<<<dim3(BT, 4), NTHR, smem_bytes>>>(P);
    mix_kernel<<<BT / 8, 256>>>((const float*)d_in[0], (float*)d_out);
}

// round 12
// speedup vs baseline: 1.8194x; 1.5820x over previous
#include <cuda_runtime.h>
#include <cuda_bf16.h>
#include <math.h>

#define BT   1024
#define NEN  64
#define ED   128
#define HYPD 256
#define NA   16
#define EMB  32
#define NTHR 512

typedef unsigned long long u64;
typedef unsigned int u32;

// ---------------- smem byte map (dynamic, 230720 B total) ----------------
#define X1HI_B   0        // x1 hi bf16 [64][264]  (33792 B)
#define X1LO_B   33792    // x1 lo bf16 [64][264]
#define KV_B     67584    // K then V fp32 [64][264] (67584 B)
#define EHI_B    67584    //   (alias, pre-fc1) E hi bf16 [64][136] (17408)
#define ELO_B    84992    //   E lo
#define Q_B      135168   // Q fp32 [16][256] (16384)
#define WTHI_B   151552   // weight tile hi bf16 [256][24] (12288)
#define WTLO_B   163840   // weight tile lo
#define WTF32_B  151552   //   (alias) fc2 fp32 wt [16][36] (2304)
#define L_B      176128   // logits fp32 [64][65] (16640)
#define ATHI_B   192768   // attn hi bf16 [16][264] (8448)
#define ATLO_B   201216   // attn lo
#define A2T_B    209664   // attn2^T fp32 [256][18] (18432)
#define X3_B     228096   // x3 fp32 [16][32] (2048)
#define EM_B     230144
#define AM_B     230400
#define INV_B    230464
#define SMEM_BYTES 230720

#define X1_STB  528
#define E_STB   272
#define AT_STB  528
#define KV_ST   264
#define Q_ST    256

// ---------------- helpers ----------------
__device__ __forceinline__ void ffma2(u64 &d, u64 a, u64 b) {
    asm("fma.rn.f32x2 %0, %1, %2, %0;" : "+l"(d) : "l"(a), "l"(b));
}
__device__ __forceinline__ u64 splat2(float x) {
    u64 r; asm("mov.b64 %0, {%1, %1};" : "=l"(r) : "f"(x)); return r;
}
__device__ __forceinline__ float2 unpack2(u64 v) {
    float lo, hi; asm("mov.b64 {%0, %1}, %2;" : "=f"(lo), "=f"(hi) : "l"(v));
    return make_float2(lo, hi);
}
// split two floats into packed-bf16 hi pair + lo pair (lane order: x low)
__device__ __forceinline__ void bfsplit2(float x, float y, u32 &hi, u32 &lo) {
    __nv_bfloat16 hx = __float2bfloat16_rn(x);
    __nv_bfloat16 hy = __float2bfloat16_rn(y);
    float rx = x - __bfloat162float(hx);
    float ry = y - __bfloat162float(hy);
    __nv_bfloat162 H; H.x = hx; H.y = hy;
    __nv_bfloat162 L = __floats2bfloat162_rn(rx, ry);
    hi = *reinterpret_cast<u32*>(&H);
    lo = *reinterpret_cast<u32*>(&L);
}

#define LDSM4(R0,R1,R2,R3,ADDR) \
    asm volatile("ldmatrix.sync.aligned.m8n8.x4.shared.b16 {%0,%1,%2,%3}, [%4];" \
        : "=r"(R0), "=r"(R1), "=r"(R2), "=r"(R3) : "r"(ADDR))

#define MMA16816(C, A0,A1,A2,A3, B0,B1) \
    asm volatile("mma.sync.aligned.m16n8k16.row.col.f32.bf16.bf16.f32 " \
        "{%0,%1,%2,%3}, {%4,%5,%6,%7}, {%8,%9}, {%0,%1,%2,%3};" \
        : "+f"((C)[0]), "+f"((C)[1]), "+f"((C)[2]), "+f"((C)[3]) \
        : "r"(A0), "r"(A1), "r"(A2), "r"(A3), "r"(B0), "r"(B1))

// -------- global scratch --------
__device__ float g_w1[BT * NA * EMB];
__device__ float g_b1[BT * EMB];
__device__ float g_wf[BT * EMB];
__device__ float g_vv[BT];

struct Ptrs { const float* p[31]; };

extern __shared__ char smemc[];

// ---------------------------------------------------------------------
// bf16-split warp MMA GEMM: out[R][256] = epi(A[R][K] @ gW[256][K]^T)
// R = NMB*16 (NMB=4 -> 64 rows, NMB=1 -> 16 rows). 16 warps.
// A: bf16 hi/lo in smem, row-major, stride aStrideB bytes.
// Weight tiles (KT=16) staged per step into wtHi/wtLo ([c][24] bf16).
// EPI: 0 = fp32 row-major (no bias); 1 = bias+relu -> bf16 hi/lo;
//      2 = bias+agent-mask -> fp32 transposed stride 18.
// ---------------------------------------------------------------------
template<int NMB, int KDIM, int EPI>
__device__ __forceinline__ void mma_gemm(
    u32 aHiB, u32 aLoB, int aStrideB,
    const float* __restrict__ gW, const float* __restrict__ gB,
    float* __restrict__ outF, int outStrideF,
    u32 outHiB, u32 outLoB, int outStrideB,
    float* __restrict__ a2t, const float* __restrict__ sAm,
    int tid)
{
    constexpr int NPW = (NMB == 4) ? 4 : 1;    // 16-col pairs per warp
    constexpr int NT  = KDIM / 16;
    const int wid  = tid >> 5;
    const int lane = tid & 31;
    int mb, np0;
    if (NMB == 4) { mb = wid & 3; np0 = (wid >> 2) * 4; }
    else          { mb = 0;       np0 = wid; }

    const int lr = (lane & 7) + ((lane & 8) ? 8 : 0);
    const int lk = (lane & 16) ? 16 : 0;
    u32 sb = (u32)__cvta_generic_to_shared(smemc);

    u32 aHiAddr = sb + aHiB + (mb * 16 + lr) * aStrideB + lk;
    u32 aLoAddr = sb + aLoB + (mb * 16 + lr) * aStrideB + lk;
    u32 bHiAddr[NPW], bLoAddr[NPW];
#pragma unroll
    for (int p = 0; p < NPW; p++) {
        int off = ((np0 + p) * 16 + lr) * 48 + lk;
        bHiAddr[p] = sb + WTHI_B + off;
        bLoAddr[p] = sb + WTLO_B + off;
    }

    float C[2 * NPW][4];
#pragma unroll
    for (int i = 0; i < 2 * NPW; i++)
#pragma unroll
        for (int j = 0; j < 4; j++) C[i][j] = 0.f;

    // prefetch tile 0 (2 float4/thread: task -> c = task>>2, g = task&3)
    float4 st[2];
#pragma unroll
    for (int l = 0; l < 2; l++) {
        int task = tid + l * NTHR;
        st[l] = *(const float4*)(gW + (task >> 2) * KDIM + 4 * (task & 3));
    }

    for (int t = 0; t < NT; t++) {
        __syncthreads();
#pragma unroll
        for (int l = 0; l < 2; l++) {
            int task = tid + l * NTHR;
            int c = task >> 2, g = task & 3;
            u32 h01, l01, h23, l23;
            bfsplit2(st[l].x, st[l].y, h01, l01);
            bfsplit2(st[l].z, st[l].w, h23, l23);
            *(uint2*)(smemc + WTHI_B + c * 48 + 8 * g) = make_uint2(h01, h23);
            *(uint2*)(smemc + WTLO_B + c * 48 + 8 * g) = make_uint2(l01, l23);
        }
        __syncthreads();
        if (t + 1 < NT) {
#pragma unroll
            for (int l = 0; l < 2; l++) {
                int task = tid + l * NTHR;
                st[l] = *(const float4*)(gW + (task >> 2) * KDIM + (t + 1) * 16 + 4 * (task & 3));
            }
        }
        u32 a0, a1, a2, a3, q0, q1, q2, q3;
        LDSM4(a0, a1, a2, a3, aHiAddr + t * 32);
        LDSM4(q0, q1, q2, q3, aLoAddr + t * 32);
#pragma unroll
        for (int p = 0; p < NPW; p++) {
            u32 bh0, bh1, bh2, bh3, bl0, bl1, bl2, bl3;
            LDSM4(bh0, bh1, bh2, bh3, bHiAddr[p]);
            LDSM4(bl0, bl1, bl2, bl3, bLoAddr[p]);
            MMA16816(C[2 * p],     a0, a1, a2, a3, bh0, bh2);
            MMA16816(C[2 * p],     a0, a1, a2, a3, bl0, bl2);
            MMA16816(C[2 * p],     q0, q1, q2, q3, bh0, bh2);
            MMA16816(C[2 * p + 1], a0, a1, a2, a3, bh1, bh3);
            MMA16816(C[2 * p + 1], a0, a1, a2, a3, bl1, bl3);
            MMA16816(C[2 * p + 1], q0, q1, q2, q3, bh1, bh3);
        }
    }

    // epilogue
    const int gid = lane >> 2, tig = lane & 3;
    const int r0 = mb * 16 + gid;
    const int r1 = r0 + 8;
#pragma unroll
    for (int p = 0; p < NPW; p++) {
#pragma unroll
        for (int s = 0; s < 2; s++) {
            const float* cf = C[2 * p + s];
            int cc = (np0 + p) * 16 + s * 8 + 2 * tig;
            if (EPI == 0) {
                *(float2*)(outF + r0 * outStrideF + cc) = make_float2(cf[0], cf[1]);
                *(float2*)(outF + r1 * outStrideF + cc) = make_float2(cf[2], cf[3]);
            } else if (EPI == 1) {
                float b0 = gB[cc], b1 = gB[cc + 1];
                float v0 = fmaxf(cf[0] + b0, 0.f), v1 = fmaxf(cf[1] + b1, 0.f);
                float v2 = fmaxf(cf[2] + b0, 0.f), v3 = fmaxf(cf[3] + b1, 0.f);
                u32 h, l;
                bfsplit2(v0, v1, h, l);
                *(u32*)(smemc + outHiB + r0 * outStrideB + cc * 2) = h;
                *(u32*)(smemc + outLoB + r0 * outStrideB + cc * 2) = l;
                bfsplit2(v2, v3, h, l);
                *(u32*)(smemc + outHiB + r1 * outStrideB + cc * 2) = h;
                *(u32*)(smemc + outLoB + r1 * outStrideB + cc * 2) = l;
            } else {
                float b0 = gB[cc], b1 = gB[cc + 1];
                float m0 = (sAm[r0] != 0.f) ? 0.f : 1.f;
                float m1 = (sAm[r1] != 0.f) ? 0.f : 1.f;
                a2t[cc * 18 + r0]       = (cf[0] + b0) * m0;
                a2t[(cc + 1) * 18 + r0] = (cf[1] + b1) * m0;
                a2t[cc * 18 + r1]       = (cf[2] + b0) * m1;
                a2t[(cc + 1) * 18 + r1] = (cf[3] + b1) * m1;
            }
        }
    }
}

// ---------------------------------------------------------------------
// scalar GEMM for fc2: out[R][C] = epi(A^T-stored @ gW^T + b)
// ---------------------------------------------------------------------
template<int R, int C, int K, int AST, bool AMASK>
__device__ __forceinline__ void gemmT(const float* __restrict__ sAT,
                                      const float* __restrict__ gW,
                                      const float* __restrict__ gB,
                                      float* __restrict__ sOut,
                                      float* __restrict__ wt,
                                      const float* __restrict__ sAm,
                                      int tid)
{
    constexpr int KT  = 16;
    constexpr int CP  = C + 4;
    constexpr int NCG = C / 4;
    constexpr int NRG = NTHR / NCG;
    constexpr int RPG = (R + NRG - 1) / NRG;
    static_assert(RPG == 1, "scalar path only");
    constexpr int NT  = K / KT;
    constexpr int K4  = KT / 4;
    constexpr int TOT = C * K4;

    const int cg = tid % NCG;
    const int rg = tid / NCG;
    const int c0 = cg * 4;
    const bool active = (rg < R);

    int idx = tid;
    bool sp = (idx < TOT);
    int sc  = sp ? (idx / K4) : 0;
    int sk4 = sp ? (idx % K4) : 0;

    float acc[4] = {0.f, 0.f, 0.f, 0.f};
    float4 stg;
    if (sp) stg = *(const float4*)(gW + sc * K + 4 * sk4);

    for (int t = 0; t < NT; t++) {
        const int k0 = t * KT;
        __syncthreads();
        if (sp) {
            int kb = 4 * sk4;
            wt[(kb + 0) * CP + sc] = stg.x;
            wt[(kb + 1) * CP + sc] = stg.y;
            wt[(kb + 2) * CP + sc] = stg.z;
            wt[(kb + 3) * CP + sc] = stg.w;
        }
        __syncthreads();
        if (t + 1 < NT && sp)
            stg = *(const float4*)(gW + sc * K + (k0 + KT) + 4 * sk4);
        if (active) {
#pragma unroll
            for (int k = 0; k < KT; k++) {
                const float4 w4 = *(const float4*)(wt + k * CP + c0);
                float a = sAT[(k0 + k) * AST + rg];
                acc[0] += a * w4.x;
                acc[1] += a * w4.y;
                acc[2] += a * w4.z;
                acc[3] += a * w4.w;
            }
        }
    }
    if (active) {
        float m = 1.f;
        if (AMASK) m = (sAm[rg] != 0.f) ? 0.f : 1.f;
#pragma unroll
        for (int j = 0; j < 4; j++) {
            float v = acc[j] + gB[c0 + j];
            sOut[rg * C + c0 + j] = v * m;
        }
    }
}

// ---------------------------------------------------------------------
__global__ void __launch_bounds__(NTHR)
hyper_kernel(Ptrs P)
{
    const int b   = blockIdx.x;
    const int h   = blockIdx.y;
    const int tid = threadIdx.x;

    const float* entities = P.p[1];
    const int*   emask    = (const int*)P.p[2];
    const int    base     = 3 + h * 7;
    const float* fc1_w = P.p[base + 0];
    const float* fc1_b = P.p[base + 1];
    const float* qkv_w = P.p[base + 2];
    const float* out_w = P.p[base + 3];
    const float* out_b = P.p[base + 4];
    const float* fc2_w = P.p[base + 5];
    const float* fc2_b = P.p[base + 6];

    float* sKVf  = (float*)(smemc + KV_B);
    float* sQf   = (float*)(smemc + Q_B);
    float* sLf   = (float*)(smemc + L_B);
    float* sA2Tf = (float*)(smemc + A2T_B);
    float* sX3f  = (float*)(smemc + X3_B);
    float* sWTf  = (float*)(smemc + WTF32_B);
    float* sEm   = (float*)(smemc + EM_B);
    float* sAm   = (float*)(smemc + AM_B);
    float* sInv  = (float*)(smemc + INV_B);

    __shared__ int sAnyZero;
    if (tid == 0) sAnyZero = 0;
    __syncthreads();

    if (tid < NEN) {
        int m = emask[b * NEN + tid];
        sEm[tid] = (float)m;
        if (tid < NA) sAm[tid] = (float)m;
        if (m == 0) atomicOr(&sAnyZero, 1);
    }
    // entities -> E hi/lo bf16 [64][136]
    {
        const float* eb = entities + (size_t)b * NEN * ED;
#pragma unroll
        for (int l = 0; l < 4; l++) {
            int task = tid + l * NTHR;     // 2048 float4 tasks
            int r = task >> 5, q = task & 31;
            float4 v = *(const float4*)(eb + r * ED + 4 * q);
            u32 h01, l01, h23, l23;
            bfsplit2(v.x, v.y, h01, l01);
            bfsplit2(v.z, v.w, h23, l23);
            *(uint2*)(smemc + EHI_B + r * E_STB + 8 * q) = make_uint2(h01, h23);
            *(uint2*)(smemc + ELO_B + r * E_STB + 8 * q) = make_uint2(l01, l23);
        }
    }
    __syncthreads();

    // fc1: x1 = relu(E @ fc1_w^T + b) -> x1 hi/lo bf16
    mma_gemm<4, 128, 1>(EHI_B, ELO_B, E_STB, fc1_w, fc1_b,
                        nullptr, 0, X1HI_B, X1LO_B, X1_STB, nullptr, nullptr, tid);
    __syncthreads();

    // Q: rows 0-15 of x1 @ Wq^T -> sQ fp32
    mma_gemm<1, 256, 0>(X1HI_B, X1LO_B, X1_STB, qkv_w, nullptr,
                        sQf, Q_ST, 0, 0, 0, nullptr, nullptr, tid);
    __syncthreads();

    // K: x1 @ Wk^T -> sKV fp32
    mma_gemm<4, 256, 0>(X1HI_B, X1LO_B, X1_STB, qkv_w + 256 * 256, nullptr,
                        sKVf, KV_ST, 0, 0, 0, nullptr, nullptr, tid);
    __syncthreads();

    const int anyZero = sAnyZero;

    // attention phase 1: logits
    {
        const int jg = tid >> 6;
        const int hq = tid & 63;
        const int hh = hq >> 4;
        const int i  = hq & 15;
        const float am_i = sAm[i];
        const float scale = 0.125f;

        u64 qp[32];
        const ulonglong2* qrow = (const ulonglong2*)(sQf + i * Q_ST + hh * 64);
#pragma unroll
        for (int d4 = 0; d4 < 16; d4++) {
            ulonglong2 q = qrow[d4];
            qp[2 * d4 + 0] = q.x;
            qp[2 * d4 + 1] = q.y;
        }
#pragma unroll
        for (int jj = 0; jj < 8; jj++) {
            int j = jg * 8 + jj;
            const ulonglong2* krow = (const ulonglong2*)(sKVf + j * KV_ST + hh * 64);
            u64 a0 = 0ULL, a1 = 0ULL;
#pragma unroll
            for (int d4 = 0; d4 < 16; d4++) {
                ulonglong2 kv = krow[d4];
                ffma2(a0, qp[2 * d4 + 0], kv.x);
                ffma2(a1, qp[2 * d4 + 1], kv.y);
            }
            float2 f0 = unpack2(a0);
            float2 f1 = unpack2(a1);
            float s = (f0.x + f0.y) + (f1.x + f1.y);
            const bool keep = (am_i == 0.f) && (sEm[j] == 0.f);
            sLf[hq * 65 + j] = keep ? (s * scale) : -1e30f;
        }
    }
    __syncthreads();

    // phase 2: softmax
    if (tid < 64) {
        const int hq = tid;
        const int i  = hq & 15;
        const float am_i = sAm[i];
        const bool allm = (am_i != 0.f) || (anyZero == 0);
        float* lrow = sLf + hq * 65;
        float mx = -1e30f;
        for (int j = 0; j < NEN; j++) mx = fmaxf(mx, lrow[j]);
        float sum = 0.f;
        for (int j = 0; j < NEN; j++) {
            float e = expf(lrow[j] - mx);
            sum += e;
            lrow[j] = e;
        }
        sInv[hq] = allm ? 0.f : (1.f / sum);
    }
    __syncthreads();

    // V: x1 @ Wv^T -> sKV fp32 (K is dead)
    mma_gemm<4, 256, 0>(X1HI_B, X1LO_B, X1_STB, qkv_w + 512 * 256, nullptr,
                        sKVf, KV_ST, 0, 0, 0, nullptr, nullptr, tid);
    __syncthreads();

    // phase 3: AV -> attn bf16 hi/lo
    {
        const int dg = tid >> 6;
        const int hq = tid & 63;
        const int hh = hq >> 4;
        const int i  = hq & 15;
        const int d0 = dg * 8;
        const float* lrow = sLf + hq * 65;
        u64 acc[4] = {0ULL, 0ULL, 0ULL, 0ULL};
        for (int j = 0; j < NEN; j++) {
            u64 ps = splat2(lrow[j]);
            const ulonglong2* vrow = (const ulonglong2*)(sKVf + j * KV_ST + hh * 64 + d0);
            ulonglong2 va = vrow[0];
            ulonglong2 vb = vrow[1];
            ffma2(acc[0], ps, va.x);
            ffma2(acc[1], ps, va.y);
            ffma2(acc[2], ps, vb.x);
            ffma2(acc[3], ps, vb.y);
        }
        const float inv = sInv[hq];
#pragma unroll
        for (int q = 0; q < 4; q++) {
            float2 f = unpack2(acc[q]);
            int c = hh * 64 + d0 + 2 * q;
            u32 hp, lp;
            bfsplit2(f.x * inv, f.y * inv, hp, lp);
            *(u32*)(smemc + ATHI_B + i * AT_STB + c * 2) = hp;
            *(u32*)(smemc + ATLO_B + i * AT_STB + c * 2) = lp;
        }
    }
    __syncthreads();

    // out projection: attn @ out_w^T + b, masked -> attn2^T fp32 [256][18]
    mma_gemm<1, 256, 2>(ATHI_B, ATLO_B, AT_STB, out_w, out_b,
                        nullptr, 0, 0, 0, 0, sA2Tf, sAm, tid);
    __syncthreads();

    // fc2 scalar: x3[16][32]
    gemmT<16, 32, 256, 18, true>(sA2Tf, fc2_w, fc2_b, sX3f, sWTf, sAm, tid);
    __syncthreads();

    // reductions
    if (h == 0) {
        for (int idx = tid; idx < NA * EMB; idx += NTHR)
            g_w1[(size_t)b * NA * EMB + idx] = fabsf(sX3f[idx]);
    } else if (h == 1) {
        if (tid < EMB) {
            float s = 0.f;
            for (int i = 0; i < NA; i++) s += sX3f[i * EMB + tid];
            g_b1[b * EMB + tid] = s * (1.f / 16.f);
        }
    } else if (h == 2) {
        if (tid < EMB) {
            float s = 0.f;
            for (int i = 0; i < NA; i++) s += sX3f[i * EMB + tid];
            g_wf[b * EMB + tid] = fabsf(s * (1.f / 16.f));
        }
    } else {
        if (tid < EMB) {
            float s = 0.f;
            for (int i = 0; i < NA; i++) s += sX3f[i * EMB + tid];
            sInv[tid] = s;
        }
        __syncthreads();
        if (tid == 0) {
            float t = 0.f;
            for (int e = 0; e < EMB; e++) t += sInv[e];
            g_vv[b] = t * (1.f / 512.f);
        }
    }
}

// ---------------------------------------------------------------------
__global__ void __launch_bounds__(256)
mix_kernel(const float* __restrict__ qs, float* __restrict__ out)
{
    const int warp = threadIdx.x >> 5;
    const int lane = threadIdx.x & 31;
    const int b = blockIdx.x * 8 + warp;
    const int e = lane;

    float s = g_b1[b * EMB + e];
#pragma unroll
    for (int a = 0; a < NA; a++)
        s += qs[b * NA + a] * g_w1[(b * NA + a) * EMB + e];
    float hdn = (s > 0.f) ? s : expm1f(s);
    float t = hdn * g_wf[b * EMB + e];
#pragma unroll
    for (int off = 16; off > 0; off >>= 1)
        t += __shfl_xor_sync(0xFFFFFFFF, t, off);
    if (lane == 0) out[b] = t + g_vv[b];
}

// ---------------------------------------------------------------------
extern "C" void kernel_launch(void* const* d_in, const int* in_sizes, int n_in,
                              void* d_out, int out_size)
{
    Ptrs P;
    for (int i = 0; i < 31; i++) P.p[i] = (const float*)d_in[i];

    cudaFuncSetAttribute(hyper_kernel,
                         cudaFuncAttributeMaxDynamicSharedMemorySize,
                         SMEM_BYTES);

    hyper_kernel<<<dim3(BT, 4), NTHR, SMEM_BYTES>>>(P);
    mix_kernel<<<BT / 8, 256>>>((const float*)d_in[0], (float*)d_out);
}